// round 15
// baseline (speedup 1.0000x reference)
#include <cuda_runtime.h>
#include <cuda_fp16.h>
#include <cstdint>

#define BSZ 2
#define SEQL 2048
#define EMB 1024
#define NH 16
#define HD 64
#define MROWS (BSZ * SEQL)

// ---------------- scratch (__device__ globals; no allocs allowed) ----------
__device__ __half g_x16[MROWS * EMB];
__device__ __half g_a16[MROWS * EMB];
__device__ __half g_wq16[EMB * EMB], g_wk16[EMB * EMB];
__device__ __half g_wv16[EMB * EMB], g_wo16[EMB * EMB];
__device__ __half g_q16[BSZ * NH * SEQL * HD];
__device__ __half g_k16[BSZ * NH * SEQL * HD];
__device__ __half g_v16[BSZ * NH * SEQL * HD];

// ---------------- PTX helpers (family-compatible, sm_80-era) ----------------
__device__ __forceinline__ uint32_t s2u(const void* p) {
    uint32_t a;
    asm("{ .reg .u64 t; cvta.to.shared.u64 t, %1; cvt.u32.u64 %0, t; }"
        : "=r"(a) : "l"(p));
    return a;
}
__device__ __forceinline__ void cpa16(uint32_t d, const void* g) {
    asm volatile("cp.async.cg.shared.global [%0], [%1], 16;" :: "r"(d), "l"(g));
}
#define CP_COMMIT() asm volatile("cp.async.commit_group;" ::: "memory")
#define CP_WAIT(n) asm volatile("cp.async.wait_group %0;" :: "n"(n) : "memory")

__device__ __forceinline__ void ldsm4(uint32_t* r, uint32_t a) {
    asm volatile("ldmatrix.sync.aligned.m8n8.x4.shared.b16 {%0,%1,%2,%3}, [%4];"
                 : "=r"(r[0]), "=r"(r[1]), "=r"(r[2]), "=r"(r[3]) : "r"(a));
}
__device__ __forceinline__ void ldsm2t(uint32_t* r, uint32_t a) {
    asm volatile("ldmatrix.sync.aligned.m8n8.x2.trans.shared.b16 {%0,%1}, [%2];"
                 : "=r"(r[0]), "=r"(r[1]) : "r"(a));
}
__device__ __forceinline__ void mma_f16(float* c, const uint32_t* a, const uint32_t* b) {
    asm volatile(
        "mma.sync.aligned.m16n8k16.row.col.f32.f16.f16.f32 "
        "{%0,%1,%2,%3}, {%4,%5,%6,%7}, {%8,%9}, {%0,%1,%2,%3};"
        : "+f"(c[0]), "+f"(c[1]), "+f"(c[2]), "+f"(c[3])
        : "r"(a[0]), "r"(a[1]), "r"(a[2]), "r"(a[3]), "r"(b[0]), "r"(b[1]));
}

// ---------------- all fp32 -> fp16 conversions in ONE kernel ----------------
__global__ __launch_bounds__(256) void cvt_all(
    const float* __restrict__ x, const float* __restrict__ wq,
    const float* __restrict__ wk, const float* __restrict__ wv,
    const float* __restrict__ wo,
    __half* __restrict__ x16, __half* __restrict__ wq16,
    __half* __restrict__ wk16, __half* __restrict__ wv16,
    __half* __restrict__ wo16) {
    const int b = blockIdx.x;
    const float* in;
    __half* out;
    int i;
    if (b < 4096) {
        in = x; out = x16; i = b * 256 + threadIdx.x;
    } else {
        const int w = (b - 4096) >> 10;
        i = ((b - 4096) & 1023) * 256 + threadIdx.x;
        in = (w == 0) ? wq : (w == 1) ? wk : (w == 2) ? wv : wo;
        out = (w == 0) ? wq16 : (w == 1) ? wk16 : (w == 2) ? wv16 : wo16;
    }
    float4 v = ((const float4*)in)[i];
    __half2 a = __floats2half2_rn(v.x, v.y);
    __half2 c = __floats2half2_rn(v.z, v.w);
    ((uint32_t*)out)[2 * i] = *(uint32_t*)&a;
    ((uint32_t*)out)[2 * i + 1] = *(uint32_t*)&c;
}

// ---------------- fp16 GEMM common config -----------------------------------
// CTA tile 128x128, BK=64, 3-stage cp.async ring (wait<=1 -> ~2-chunk slack).
#define TM 128
#define TN 128
#define KB 64
#define NCH (EMB / KB)               // 16
#define ROWB 144                     // 64 halfs = 128B data + 16B pad
#define MAT_B (128 * ROWB)           // 18432
#define OFF_A 0
#define OFF_B MAT_B
#define STAGE_B (2 * MAT_B)          // 36864
#define NSTG 3
#define SM_TOTAL (NSTG * STAGE_B)    // 110592

// Fragment loads for one k16 step: 2 A-ldsm4 + 4 B-ldsm4.
#define LOAD_FRAGS(st, kk, ah, bq)                                              \
    do {                                                                        \
        _Pragma("unroll") for (int mf = 0; mf < 2; mf++)                        \
            ldsm4((ah)[mf],                                                     \
                  (st) + OFF_A + (aRow + mf * 16) * ROWB + (kk) * 32 + xHalf);  \
        _Pragma("unroll") for (int nfp = 0; nfp < 4; nfp++)                     \
            ldsm4((bq)[nfp],                                                    \
                  (st) + OFF_B + (bRow + nfp * 16) * ROWB + (kk) * 32 + xHalf); \
    } while (0)

#define DO_MMAS(ah, bq, acc)                                                    \
    do {                                                                        \
        _Pragma("unroll") for (int nfp = 0; nfp < 4; nfp++) {                   \
            uint32_t be[2] = {(bq)[nfp][0], (bq)[nfp][2]};                      \
            uint32_t bo[2] = {(bq)[nfp][1], (bq)[nfp][3]};                      \
            _Pragma("unroll") for (int mf = 0; mf < 2; mf++) {                  \
                mma_f16((acc)[mf][2 * nfp], (ah)[mf], be);                      \
                mma_f16((acc)[mf][2 * nfp + 1], (ah)[mf], bo);                  \
            }                                                                   \
        }                                                                       \
    } while (0)

// 3-stage ring: compute c, c+1 in flight, c+2 being issued.
#define GEMM_MAINLOOP(load_chunk)                                               \
    load_chunk(0, 0);                                                           \
    load_chunk(1, 1);                                                           \
    for (int c = 0; c < NCH; c++) {                                             \
        if (c + 2 < NCH) { CP_WAIT(1); } else { CP_WAIT(0); }                   \
        __syncthreads();                                                        \
        if (c + 2 < NCH) {                                                      \
            int nst = c + 2 - ((c + 2) / 3) * 3;                                \
            load_chunk(c + 2, nst);                                             \
        }                                                                       \
        const uint32_t st = sb + (c - (c / 3) * 3) * STAGE_B;                   \
        _Pragma("unroll") for (int kk = 0; kk < 4; kk++) {                      \
            uint32_t ah[2][4], bq[4][4];                                        \
            LOAD_FRAGS(st, kk, ah, bq);                                         \
            DO_MMAS(ah, bq, acc);                                               \
        }                                                                       \
    }

// ---------------- fused QKV GEMM: {Q,K,V} = x @ W^T, scatter [b,h,s,d] -------
__global__ __launch_bounds__(256, 2)
void gemm_qkv(const __half* __restrict__ A16,
              const __half* __restrict__ Wq, const __half* __restrict__ Wk,
              const __half* __restrict__ Wv,
              __half* __restrict__ Qo, __half* __restrict__ Ko,
              __half* __restrict__ Vo) {
    extern __shared__ __align__(128) char smem[];
    const uint32_t sb = s2u(smem);
    const int tid = threadIdx.x;
    const int wid = tid >> 5;
    const int lane = tid & 31;
    const int w = blockIdx.x >> 3;
    const int n0 = (blockIdx.x & 7) * TN;
    const int m0 = blockIdx.y * TM;
    const __half* B16 = (w == 0) ? Wq : (w == 1) ? Wk : Wv;
    __half* Ch = (w == 0) ? Qo : (w == 1) ? Ko : Vo;
    const int wm0 = (wid >> 1) * 32;
    const int wn0 = (wid & 1) * 64;

    // load geometry: row = tid>>1 (0..127), 4 x 16B chunks at (tid&1)*4
    const int lr = tid >> 1;
    const int lcw = (tid & 1) * 4;
    const __half* pA = A16 + (size_t)(m0 + lr) * EMB + lcw * 8;
    const __half* pB = B16 + (size_t)(n0 + lr) * EMB + lcw * 8;
    const uint32_t so0 = lr * ROWB + lcw * 16;

    auto load_chunk = [&](int c, int s) {
        const uint32_t base = sb + s * STAGE_B;
        const int kb = c * KB;
#pragma unroll
        for (int i = 0; i < 4; i++) {
            cpa16(base + OFF_A + so0 + i * 16, pA + kb + i * 8);
            cpa16(base + OFF_B + so0 + i * 16, pB + kb + i * 8);
        }
        CP_COMMIT();
    };

    float acc[2][8][4];
#pragma unroll
    for (int mf = 0; mf < 2; mf++)
#pragma unroll
        for (int nf = 0; nf < 8; nf++)
#pragma unroll
            for (int j = 0; j < 4; j++) acc[mf][nf][j] = 0.0f;

    const uint32_t aRow = wm0 + (lane & 15);
    const uint32_t xHalf = (lane >> 4) * 16;
    const uint32_t bRow = wn0 + (lane & 15);

    GEMM_MAINLOOP(load_chunk)

#pragma unroll
    for (int mf = 0; mf < 2; mf++) {
        const int mrow = m0 + wm0 + mf * 16 + (lane >> 2);
#pragma unroll
        for (int half = 0; half < 2; half++) {
            const int row = mrow + half * 8;
            const int b = row >> 11;
            const int sdx = row & (SEQL - 1);
#pragma unroll
            for (int nf = 0; nf < 8; nf++) {
                const int col = n0 + wn0 + nf * 8 + 2 * (lane & 3);
                const int h = col >> 6;
                const int d = col & 63;
                const size_t idx = (((size_t)(b * NH + h) * SEQL + sdx) << 6) + d;
                __half2 hv2 = __floats2half2_rn(acc[mf][nf][2 * half],
                                                acc[mf][nf][2 * half + 1]);
                *(uint32_t*)&Ch[idx] = *(uint32_t*)&hv2;
            }
        }
    }
}

// ---------------- output-projection GEMM: out = attn @ Wo^T (fp32 out) ------
__global__ __launch_bounds__(256, 2)
void gemm_out(const __half* __restrict__ A16, const __half* __restrict__ B16,
              float* __restrict__ C) {
    extern __shared__ __align__(128) char smem[];
    const uint32_t sb = s2u(smem);
    const int tid = threadIdx.x;
    const int wid = tid >> 5;
    const int lane = tid & 31;
    const int m0 = blockIdx.y * TM;
    const int n0 = blockIdx.x * TN;
    const int wm0 = (wid >> 1) * 32;
    const int wn0 = (wid & 1) * 64;

    const int lr = tid >> 1;
    const int lcw = (tid & 1) * 4;
    const __half* pA = A16 + (size_t)(m0 + lr) * EMB + lcw * 8;
    const __half* pB = B16 + (size_t)(n0 + lr) * EMB + lcw * 8;
    const uint32_t so0 = lr * ROWB + lcw * 16;

    auto load_chunk = [&](int c, int s) {
        const uint32_t base = sb + s * STAGE_B;
        const int kb = c * KB;
#pragma unroll
        for (int i = 0; i < 4; i++) {
            cpa16(base + OFF_A + so0 + i * 16, pA + kb + i * 8);
            cpa16(base + OFF_B + so0 + i * 16, pB + kb + i * 8);
        }
        CP_COMMIT();
    };

    float acc[2][8][4];
#pragma unroll
    for (int mf = 0; mf < 2; mf++)
#pragma unroll
        for (int nf = 0; nf < 8; nf++)
#pragma unroll
            for (int j = 0; j < 4; j++) acc[mf][nf][j] = 0.0f;

    const uint32_t aRow = wm0 + (lane & 15);
    const uint32_t xHalf = (lane >> 4) * 16;
    const uint32_t bRow = wn0 + (lane & 15);

    GEMM_MAINLOOP(load_chunk)

#pragma unroll
    for (int mf = 0; mf < 2; mf++) {
        const int mrow = m0 + wm0 + mf * 16 + (lane >> 2);
#pragma unroll
        for (int half = 0; half < 2; half++) {
            const int row = mrow + half * 8;
#pragma unroll
            for (int nf = 0; nf < 8; nf++) {
                const int col = n0 + wn0 + nf * 8 + 2 * (lane & 3);
                float2 v = {acc[mf][nf][2 * half], acc[mf][nf][2 * half + 1]};
                *(float2*)&C[(size_t)row * EMB + col] = v;
            }
        }
    }
}

// ---------------- tensor-core causal flash attention (single fp16) ----------
#define QT 128
#define ST 64
#define KROWB 144
#define KVTILE (ST * KROWB)          // 9216
#define AT_STAGE (2 * KVTILE)        // 18432
#define AT_SMEM (2 * AT_STAGE)       // 36864
#define QSTG (QT * KROWB)            // 18432

__global__ __launch_bounds__(256, 2)
void attn_mma(const __half* __restrict__ Q16, const __half* __restrict__ K16,
              const __half* __restrict__ V16, __half* __restrict__ O16) {
    extern __shared__ __align__(128) char smem[];
    const uint32_t sb = s2u(smem);
    const int tid = threadIdx.x;
    const int wid = tid >> 5;
    const int lane = tid & 31;
    const int qt = (SEQL / QT - 1) - (blockIdx.x >> 5);  // heavy tiles first
    const int bh = blockIdx.x & 31;
    const size_t hoff = (size_t)bh * SEQL * HD;

    {
        const int r = tid >> 1;
        const int cs = (tid & 1) * 4;
        const __half* qp = Q16 + hoff + (size_t)(qt * QT + r) * HD + cs * 8;
#pragma unroll
        for (int i = 0; i < 4; i++)
            cpa16(sb + r * KROWB + (cs + i) * 16, qp + i * 8);
        CP_COMMIT();
        CP_WAIT(0);
        __syncthreads();
    }
    uint32_t qa[4][4];
    {
        const uint32_t qa0 = (16 * wid + (lane & 15)) * KROWB + (lane >> 4) * 16;
#pragma unroll
        for (int kk = 0; kk < 4; kk++) ldsm4(qa[kk], sb + qa0 + kk * 32);
    }
    __syncthreads();

    auto load_kv = [&](int c, int stg) {
        const uint32_t base = sb + stg * AT_STAGE;
        const size_t g0 = hoff + (size_t)(c * ST) * HD;
#pragma unroll
        for (int i = 0; i < 2; i++) {
            const int id = tid + 256 * i;
            const int r = id >> 3;
            const int sg = id & 7;
            const uint32_t so = r * KROWB + sg * 16;
            const size_t go = g0 + (size_t)r * HD + sg * 8;
            cpa16(base + so, K16 + go);
            cpa16(base + KVTILE + so, V16 + go);
        }
        CP_COMMIT();
    };

    float m_[2] = {-1e30f, -1e30f};
    float l_[2] = {0.0f, 0.0f};
    float o[8][4];
#pragma unroll
    for (int nf = 0; nf < 8; nf++)
#pragma unroll
        for (int j = 0; j < 4; j++) o[nf][j] = 0.0f;

    const int nch = 2 * qt + 2;
    load_kv(0, 0);
    if (nch > 1) load_kv(1, 1);

    const int rowa = qt * QT + 16 * wid + (lane >> 2);
    const uint32_t xHalf = (lane >> 4) * 16;

    for (int c = 0; c < nch; c++) {
        if (c + 1 < nch) { CP_WAIT(1); } else { CP_WAIT(0); }
        __syncthreads();
        const uint32_t st = sb + (c & 1) * AT_STAGE;

        float s[8][4];
#pragma unroll
        for (int nf = 0; nf < 8; nf++)
#pragma unroll
            for (int j = 0; j < 4; j++) s[nf][j] = 0.0f;
#pragma unroll
        for (int kk = 0; kk < 4; kk++) {
#pragma unroll
            for (int nfp = 0; nfp < 4; nfp++) {
                uint32_t kq[4];
                ldsm4(kq, st + (nfp * 16 + (lane & 15)) * KROWB + kk * 32 + xHalf);
                uint32_t ke[2] = {kq[0], kq[2]};
                uint32_t ko[2] = {kq[1], kq[3]};
                mma_f16(s[2 * nfp], qa[kk], ke);
                mma_f16(s[2 * nfp + 1], qa[kk], ko);
            }
        }

        const bool diagc = (c >= 2 * qt);
#pragma unroll
        for (int nf = 0; nf < 8; nf++) {
#pragma unroll
            for (int j = 0; j < 4; j++) {
                float v = s[nf][j] * 0.125f;
                if (diagc) {
                    const int col = c * ST + nf * 8 + 2 * (lane & 3) + (j & 1);
                    const int row = rowa + ((j >> 1) << 3);
                    if (col > row) v = -1e30f;
                }
                s[nf][j] = v;
            }
        }

        float rma = -1e30f, rmb = -1e30f;
#pragma unroll
        for (int nf = 0; nf < 8; nf++) {
            rma = fmaxf(rma, fmaxf(s[nf][0], s[nf][1]));
            rmb = fmaxf(rmb, fmaxf(s[nf][2], s[nf][3]));
        }
        rma = fmaxf(rma, __shfl_xor_sync(0xffffffffu, rma, 1));
        rma = fmaxf(rma, __shfl_xor_sync(0xffffffffu, rma, 2));
        rmb = fmaxf(rmb, __shfl_xor_sync(0xffffffffu, rmb, 1));
        rmb = fmaxf(rmb, __shfl_xor_sync(0xffffffffu, rmb, 2));

        const float mna = fmaxf(m_[0], rma);
        const float mnb = fmaxf(m_[1], rmb);
        const float ca = __expf(m_[0] - mna);
        const float cb = __expf(m_[1] - mnb);
        float sa = 0.0f, sbv = 0.0f;
#pragma unroll
        for (int nf = 0; nf < 8; nf++) {
            s[nf][0] = __expf(s[nf][0] - mna);
            s[nf][1] = __expf(s[nf][1] - mna);
            s[nf][2] = __expf(s[nf][2] - mnb);
            s[nf][3] = __expf(s[nf][3] - mnb);
            sa += s[nf][0] + s[nf][1];
            sbv += s[nf][2] + s[nf][3];
        }
        sa += __shfl_xor_sync(0xffffffffu, sa, 1);
        sa += __shfl_xor_sync(0xffffffffu, sa, 2);
        sbv += __shfl_xor_sync(0xffffffffu, sbv, 1);
        sbv += __shfl_xor_sync(0xffffffffu, sbv, 2);
        l_[0] = l_[0] * ca + sa;
        l_[1] = l_[1] * cb + sbv;
        m_[0] = mna;
        m_[1] = mnb;
#pragma unroll
        for (int nf = 0; nf < 8; nf++) {
            o[nf][0] *= ca;
            o[nf][1] *= ca;
            o[nf][2] *= cb;
            o[nf][3] *= cb;
        }

#pragma unroll
        for (int kk = 0; kk < 4; kk++) {
            uint32_t ph[4];
            __half2 t0 = __floats2half2_rn(s[2 * kk][0], s[2 * kk][1]);
            __half2 t1 = __floats2half2_rn(s[2 * kk][2], s[2 * kk][3]);
            __half2 t2 = __floats2half2_rn(s[2 * kk + 1][0], s[2 * kk + 1][1]);
            __half2 t3 = __floats2half2_rn(s[2 * kk + 1][2], s[2 * kk + 1][3]);
            ph[0] = *(uint32_t*)&t0;
            ph[1] = *(uint32_t*)&t1;
            ph[2] = *(uint32_t*)&t2;
            ph[3] = *(uint32_t*)&t3;
#pragma unroll
            for (int nf = 0; nf < 8; nf++) {
                uint32_t vf[2];
                const uint32_t vo = (kk * 16 + (lane & 15)) * KROWB + nf * 16;
                ldsm2t(vf, st + KVTILE + vo);
                mma_f16(o[nf], ph, vf);
            }
        }
        __syncthreads();
        if (c + 2 < nch) load_kv(c + 2, c & 1);
    }

    const int b = bh >> 4;
    const int h = bh & 15;
    const float ia = 1.0f / l_[0];
    const float ib = 1.0f / l_[1];
#pragma unroll
    for (int nf = 0; nf < 8; nf++) {
        const int e = h * 64 + nf * 8 + 2 * (lane & 3);
        __half2 hv = __floats2half2_rn(o[nf][0] * ia, o[nf][1] * ia);
        size_t idx = (size_t)(b * SEQL + rowa) * EMB + e;
        *(uint32_t*)&O16[idx] = *(uint32_t*)&hv;
        hv = __floats2half2_rn(o[nf][2] * ib, o[nf][3] * ib);
        idx = (size_t)(b * SEQL + rowa + 8) * EMB + e;
        *(uint32_t*)&O16[idx] = *(uint32_t*)&hv;
    }
}

// ---------------- launch -----------------------------------------------------
extern "C" void kernel_launch(void* const* d_in, const int* in_sizes, int n_in,
                              void* d_out, int out_size) {
    const float* x = (const float*)d_in[0];
    const float* w_q = (const float*)d_in[1];
    const float* w_k = (const float*)d_in[2];
    const float* w_v = (const float*)d_in[3];
    const float* w_o = (const float*)d_in[4];
    float* out = (float*)d_out;

    __half *x16, *a16, *wq16, *wk16, *wv16, *wo16, *q16, *k16, *v16;
    cudaGetSymbolAddress((void**)&x16, g_x16);
    cudaGetSymbolAddress((void**)&a16, g_a16);
    cudaGetSymbolAddress((void**)&wq16, g_wq16);
    cudaGetSymbolAddress((void**)&wk16, g_wk16);
    cudaGetSymbolAddress((void**)&wv16, g_wv16);
    cudaGetSymbolAddress((void**)&wo16, g_wo16);
    cudaGetSymbolAddress((void**)&q16, g_q16);
    cudaGetSymbolAddress((void**)&k16, g_k16);
    cudaGetSymbolAddress((void**)&v16, g_v16);

    cudaFuncSetAttribute(gemm_qkv, cudaFuncAttributeMaxDynamicSharedMemorySize, SM_TOTAL);
    cudaFuncSetAttribute(gemm_out, cudaFuncAttributeMaxDynamicSharedMemorySize, SM_TOTAL);
    cudaFuncSetAttribute(attn_mma, cudaFuncAttributeMaxDynamicSharedMemorySize, AT_SMEM);

    cvt_all<<<4096 + 4 * 1024, 256>>>(x, w_q, w_k, w_v, w_o,
                                      x16, wq16, wk16, wv16, wo16);

    dim3 qkvgrid(24, 32);  // x: 3 weights x 8 n-tiles; y: 32 m-tiles
    gemm_qkv<<<qkvgrid, 256, SM_TOTAL>>>(x16, wq16, wk16, wv16, q16, k16, v16);

    attn_mma<<<(SEQL / QT) * BSZ * NH, 256, AT_SMEM>>>(q16, k16, v16, a16);

    dim3 ogrid(8, 32);
    gemm_out<<<ogrid, 256, SM_TOTAL>>>(a16, wo16, out);
}

// round 16
// speedup vs baseline: 1.0736x; 1.0736x over previous
#include <cuda_runtime.h>
#include <cuda_fp16.h>
#include <cstdint>

#define BSZ 2
#define SEQL 2048
#define EMB 1024
#define NH 16
#define HD 64
#define MROWS (BSZ * SEQL)

// ---------------- scratch (__device__ globals; no allocs allowed) ----------
__device__ __half g_x16[MROWS * EMB];
__device__ __half g_a16[MROWS * EMB];
__device__ __half g_wq16[EMB * EMB], g_wk16[EMB * EMB];
__device__ __half g_wv16[EMB * EMB], g_wo16[EMB * EMB];
__device__ __half g_q16[BSZ * NH * SEQL * HD];
__device__ __half g_k16[BSZ * NH * SEQL * HD];
__device__ __half g_v16[BSZ * NH * SEQL * HD];

// ---------------- PTX helpers (family-compatible, sm_80-era) ----------------
__device__ __forceinline__ uint32_t s2u(const void* p) {
    uint32_t a;
    asm("{ .reg .u64 t; cvta.to.shared.u64 t, %1; cvt.u32.u64 %0, t; }"
        : "=r"(a) : "l"(p));
    return a;
}
__device__ __forceinline__ void cpa16(uint32_t d, const void* g) {
    asm volatile("cp.async.cg.shared.global [%0], [%1], 16;" :: "r"(d), "l"(g));
}
#define CP_COMMIT() asm volatile("cp.async.commit_group;" ::: "memory")
#define CP_WAIT(n) asm volatile("cp.async.wait_group %0;" :: "n"(n) : "memory")

__device__ __forceinline__ void ldsm4(uint32_t* r, uint32_t a) {
    asm volatile("ldmatrix.sync.aligned.m8n8.x4.shared.b16 {%0,%1,%2,%3}, [%4];"
                 : "=r"(r[0]), "=r"(r[1]), "=r"(r[2]), "=r"(r[3]) : "r"(a));
}
__device__ __forceinline__ void ldsm2t(uint32_t* r, uint32_t a) {
    asm volatile("ldmatrix.sync.aligned.m8n8.x2.trans.shared.b16 {%0,%1}, [%2];"
                 : "=r"(r[0]), "=r"(r[1]) : "r"(a));
}
__device__ __forceinline__ void mma_f16(float* c, const uint32_t* a, const uint32_t* b) {
    asm volatile(
        "mma.sync.aligned.m16n8k16.row.col.f32.f16.f16.f32 "
        "{%0,%1,%2,%3}, {%4,%5,%6,%7}, {%8,%9}, {%0,%1,%2,%3};"
        : "+f"(c[0]), "+f"(c[1]), "+f"(c[2]), "+f"(c[3])
        : "r"(a[0]), "r"(a[1]), "r"(a[2]), "r"(a[3]), "r"(b[0]), "r"(b[1]));
}

// ---------------- all fp32 -> fp16 conversions, 4 float4 per thread ---------
// blocks [0,1024): x. blocks [1024, 1024+4*256): weights (256 blocks each).
__global__ __launch_bounds__(256) void cvt_all(
    const float* __restrict__ x, const float* __restrict__ wq,
    const float* __restrict__ wk, const float* __restrict__ wv,
    const float* __restrict__ wo,
    __half* __restrict__ x16, __half* __restrict__ wq16,
    __half* __restrict__ wk16, __half* __restrict__ wv16,
    __half* __restrict__ wo16) {
    const int b = blockIdx.x;
    const float* in;
    __half* out;
    int i0;
    if (b < 1024) {
        in = x; out = x16; i0 = b * 1024 + threadIdx.x;
    } else {
        const int w = (b - 1024) >> 8;
        i0 = ((b - 1024) & 255) * 1024 + threadIdx.x;
        in = (w == 0) ? wq : (w == 1) ? wk : (w == 2) ? wv : wo;
        out = (w == 0) ? wq16 : (w == 1) ? wk16 : (w == 2) ? wv16 : wo16;
    }
#pragma unroll
    for (int j = 0; j < 4; j++) {
        const int i = i0 + j * 256;
        float4 v = ((const float4*)in)[i];
        __half2 a = __floats2half2_rn(v.x, v.y);
        __half2 c = __floats2half2_rn(v.z, v.w);
        ((uint32_t*)out)[2 * i] = *(uint32_t*)&a;
        ((uint32_t*)out)[2 * i + 1] = *(uint32_t*)&c;
    }
}

// ---------------- fp16 GEMM common config (round-14 proven best) ------------
// CTA tile 128x128, BK=32, 4-stage cp.async ring, prefetch distance 3.
#define TM 128
#define TN 128
#define KB 32
#define NCH (EMB / KB)               // 32
#define ROWB 80                      // 32 halfs = 64B data + 16B pad
#define MAT_B (128 * ROWB)           // 10240
#define OFF_A 0
#define OFF_B MAT_B
#define STAGE_B (2 * MAT_B)          // 20480
#define NSTG 4
#define SM_TOTAL (NSTG * STAGE_B)    // 81920

// Fragment loads for one k16 step: 2 A-ldsm4 + 4 B-ldsm4.
#define LOAD_FRAGS(st, kk, ah, bq)                                              \
    do {                                                                        \
        _Pragma("unroll") for (int mf = 0; mf < 2; mf++)                        \
            ldsm4((ah)[mf],                                                     \
                  (st) + OFF_A + (aRow + mf * 16) * ROWB + (kk) * 32 + xHalf);  \
        _Pragma("unroll") for (int nfp = 0; nfp < 4; nfp++)                     \
            ldsm4((bq)[nfp],                                                    \
                  (st) + OFF_B + (bRow + nfp * 16) * ROWB + (kk) * 32 + xHalf); \
    } while (0)

#define DO_MMAS(ah, bq, acc)                                                    \
    do {                                                                        \
        _Pragma("unroll") for (int nfp = 0; nfp < 4; nfp++) {                   \
            uint32_t be[2] = {(bq)[nfp][0], (bq)[nfp][2]};                      \
            uint32_t bo[2] = {(bq)[nfp][1], (bq)[nfp][3]};                      \
            _Pragma("unroll") for (int mf = 0; mf < 2; mf++) {                  \
                mma_f16((acc)[mf][2 * nfp], (ah)[mf], be);                      \
                mma_f16((acc)[mf][2 * nfp + 1], (ah)[mf], bo);                  \
            }                                                                   \
        }                                                                       \
    } while (0)

// 4-stage ring, prefetch distance 3 (round-14 measured best).
#define GEMM_MAINLOOP(load_chunk)                                               \
    load_chunk(0, 0);                                                           \
    load_chunk(1, 1);                                                           \
    load_chunk(2, 2);                                                           \
    for (int c = 0; c < NCH; c++) {                                             \
        if (c <= NCH - 3) { CP_WAIT(2); }                                       \
        else if (c == NCH - 2) { CP_WAIT(1); }                                  \
        else { CP_WAIT(0); }                                                    \
        __syncthreads();                                                        \
        if (c + 3 < NCH) load_chunk(c + 3, (c + 3) & 3);                        \
        const uint32_t st = sb + (c & 3) * STAGE_B;                             \
        _Pragma("unroll") for (int kk = 0; kk < 2; kk++) {                      \
            uint32_t ah[2][4], bq[4][4];                                        \
            LOAD_FRAGS(st, kk, ah, bq);                                         \
            DO_MMAS(ah, bq, acc);                                               \
        }                                                                       \
    }

// ---------------- fused QKV GEMM: {Q,K,V} = x @ W^T, scatter [b,h,s,d] -------
__global__ __launch_bounds__(256, 2)
void gemm_qkv(const __half* __restrict__ A16,
              const __half* __restrict__ Wq, const __half* __restrict__ Wk,
              const __half* __restrict__ Wv,
              __half* __restrict__ Qo, __half* __restrict__ Ko,
              __half* __restrict__ Vo) {
    extern __shared__ __align__(128) char smem[];
    const uint32_t sb = s2u(smem);
    const int tid = threadIdx.x;
    const int wid = tid >> 5;
    const int lane = tid & 31;
    const int w = blockIdx.x >> 3;
    const int n0 = (blockIdx.x & 7) * TN;
    const int m0 = blockIdx.y * TM;
    const __half* B16 = (w == 0) ? Wq : (w == 1) ? Wk : Wv;
    __half* Ch = (w == 0) ? Qo : (w == 1) ? Ko : Vo;
    const int wm0 = (wid >> 1) * 32;
    const int wn0 = (wid & 1) * 64;

    const int lr = tid >> 1;
    const int lcw = (tid & 1) * 2;
    const __half* pA = A16 + (size_t)(m0 + lr) * EMB + lcw * 8;
    const __half* pB = B16 + (size_t)(n0 + lr) * EMB + lcw * 8;
    const uint32_t so0 = lr * ROWB + lcw * 16;

    auto load_chunk = [&](int c, int s) {
        const uint32_t base = sb + s * STAGE_B;
        const int kb = c * KB;
        cpa16(base + OFF_A + so0, pA + kb);
        cpa16(base + OFF_A + so0 + 16, pA + kb + 8);
        cpa16(base + OFF_B + so0, pB + kb);
        cpa16(base + OFF_B + so0 + 16, pB + kb + 8);
        CP_COMMIT();
    };

    float acc[2][8][4];
#pragma unroll
    for (int mf = 0; mf < 2; mf++)
#pragma unroll
        for (int nf = 0; nf < 8; nf++)
#pragma unroll
            for (int j = 0; j < 4; j++) acc[mf][nf][j] = 0.0f;

    const uint32_t aRow = wm0 + (lane & 15);
    const uint32_t xHalf = (lane >> 4) * 16;
    const uint32_t bRow = wn0 + (lane & 15);

    GEMM_MAINLOOP(load_chunk)

#pragma unroll
    for (int mf = 0; mf < 2; mf++) {
        const int mrow = m0 + wm0 + mf * 16 + (lane >> 2);
#pragma unroll
        for (int half = 0; half < 2; half++) {
            const int row = mrow + half * 8;
            const int b = row >> 11;
            const int sdx = row & (SEQL - 1);
#pragma unroll
            for (int nf = 0; nf < 8; nf++) {
                const int col = n0 + wn0 + nf * 8 + 2 * (lane & 3);
                const int h = col >> 6;
                const int d = col & 63;
                const size_t idx = (((size_t)(b * NH + h) * SEQL + sdx) << 6) + d;
                __half2 hv2 = __floats2half2_rn(acc[mf][nf][2 * half],
                                                acc[mf][nf][2 * half + 1]);
                *(uint32_t*)&Ch[idx] = *(uint32_t*)&hv2;
            }
        }
    }
}

// ---------------- output-projection GEMM: out = attn @ Wo^T (fp32 out) ------
__global__ __launch_bounds__(256, 2)
void gemm_out(const __half* __restrict__ A16, const __half* __restrict__ B16,
              float* __restrict__ C) {
    extern __shared__ __align__(128) char smem[];
    const uint32_t sb = s2u(smem);
    const int tid = threadIdx.x;
    const int wid = tid >> 5;
    const int lane = tid & 31;
    const int m0 = blockIdx.y * TM;
    const int n0 = blockIdx.x * TN;
    const int wm0 = (wid >> 1) * 32;
    const int wn0 = (wid & 1) * 64;

    const int lr = tid >> 1;
    const int lcw = (tid & 1) * 2;
    const __half* pA = A16 + (size_t)(m0 + lr) * EMB + lcw * 8;
    const __half* pB = B16 + (size_t)(n0 + lr) * EMB + lcw * 8;
    const uint32_t so0 = lr * ROWB + lcw * 16;

    auto load_chunk = [&](int c, int s) {
        const uint32_t base = sb + s * STAGE_B;
        const int kb = c * KB;
        cpa16(base + OFF_A + so0, pA + kb);
        cpa16(base + OFF_A + so0 + 16, pA + kb + 8);
        cpa16(base + OFF_B + so0, pB + kb);
        cpa16(base + OFF_B + so0 + 16, pB + kb + 8);
        CP_COMMIT();
    };

    float acc[2][8][4];
#pragma unroll
    for (int mf = 0; mf < 2; mf++)
#pragma unroll
        for (int nf = 0; nf < 8; nf++)
#pragma unroll
            for (int j = 0; j < 4; j++) acc[mf][nf][j] = 0.0f;

    const uint32_t aRow = wm0 + (lane & 15);
    const uint32_t xHalf = (lane >> 4) * 16;
    const uint32_t bRow = wn0 + (lane & 15);

    GEMM_MAINLOOP(load_chunk)

#pragma unroll
    for (int mf = 0; mf < 2; mf++) {
        const int mrow = m0 + wm0 + mf * 16 + (lane >> 2);
#pragma unroll
        for (int half = 0; half < 2; half++) {
            const int row = mrow + half * 8;
#pragma unroll
            for (int nf = 0; nf < 8; nf++) {
                const int col = n0 + wn0 + nf * 8 + 2 * (lane & 3);
                float2 v = {acc[mf][nf][2 * half], acc[mf][nf][2 * half + 1]};
                *(float2*)&C[(size_t)row * EMB + col] = v;
            }
        }
    }
}

// ---------------- tensor-core causal flash attention (single fp16) ----------
// 3-stage KV ring, prefetch distance 2, ONE barrier per chunk.
#define QT 128
#define ST 64
#define KROWB 144
#define KVTILE (ST * KROWB)          // 9216
#define AT_STAGE (2 * KVTILE)        // 18432
#define AT_NSTG 3
#define AT_SMEM (AT_NSTG * AT_STAGE) // 55296

__global__ __launch_bounds__(256, 2)
void attn_mma(const __half* __restrict__ Q16, const __half* __restrict__ K16,
              const __half* __restrict__ V16, __half* __restrict__ O16) {
    extern __shared__ __align__(128) char smem[];
    const uint32_t sb = s2u(smem);
    const int tid = threadIdx.x;
    const int wid = tid >> 5;
    const int lane = tid & 31;
    const int qt = (SEQL / QT - 1) - (blockIdx.x >> 5);  // heavy tiles first
    const int bh = blockIdx.x & 31;
    const size_t hoff = (size_t)bh * SEQL * HD;

    // ---- stage Q tile, move to registers ----
    {
        const int r = tid >> 1;
        const int cs = (tid & 1) * 4;
        const __half* qp = Q16 + hoff + (size_t)(qt * QT + r) * HD + cs * 8;
#pragma unroll
        for (int i = 0; i < 4; i++)
            cpa16(sb + r * KROWB + (cs + i) * 16, qp + i * 8);
        CP_COMMIT();
        CP_WAIT(0);
        __syncthreads();
    }
    uint32_t qa[4][4];
    {
        const uint32_t qa0 = (16 * wid + (lane & 15)) * KROWB + (lane >> 4) * 16;
#pragma unroll
        for (int kk = 0; kk < 4; kk++) ldsm4(qa[kk], sb + qa0 + kk * 32);
    }
    __syncthreads();  // all warps have Q in regs before KV loads overwrite

    auto load_kv = [&](int c, int stg) {
        const uint32_t base = sb + stg * AT_STAGE;
        const size_t g0 = hoff + (size_t)(c * ST) * HD;
#pragma unroll
        for (int i = 0; i < 2; i++) {
            const int id = tid + 256 * i;
            const int r = id >> 3;
            const int sg = id & 7;
            const uint32_t so = r * KROWB + sg * 16;
            const size_t go = g0 + (size_t)r * HD + sg * 8;
            cpa16(base + so, K16 + go);
            cpa16(base + KVTILE + so, V16 + go);
        }
        CP_COMMIT();
    };

    float m_[2] = {-1e30f, -1e30f};
    float l_[2] = {0.0f, 0.0f};
    float o[8][4];
#pragma unroll
    for (int nf = 0; nf < 8; nf++)
#pragma unroll
        for (int j = 0; j < 4; j++) o[nf][j] = 0.0f;

    const int nch = 2 * qt + 2;
    load_kv(0, 0);
    if (nch > 1) load_kv(1, 1);

    const int rowa = qt * QT + 16 * wid + (lane >> 2);
    const uint32_t xHalf = (lane >> 4) * 16;

    for (int c = 0; c < nch; c++) {
        if (c + 1 < nch) { CP_WAIT(1); } else { CP_WAIT(0); }
        __syncthreads();
        // prefetch into stage (c+2)%3 == stage consumed at iter c-1 (safe:
        // every thread is past this barrier => finished iter c-1 reads)
        if (c + 2 < nch) {
            const int ns = (c + 2) - ((c + 2) / 3) * 3;
            load_kv(c + 2, ns);
        }
        const uint32_t st = sb + (c - (c / 3) * 3) * AT_STAGE;

        // ---- S = Q K^T (K fragments via x4 pairs) ----
        float s[8][4];
#pragma unroll
        for (int nf = 0; nf < 8; nf++)
#pragma unroll
            for (int j = 0; j < 4; j++) s[nf][j] = 0.0f;
#pragma unroll
        for (int kk = 0; kk < 4; kk++) {
#pragma unroll
            for (int nfp = 0; nfp < 4; nfp++) {
                uint32_t kq[4];
                ldsm4(kq, st + (nfp * 16 + (lane & 15)) * KROWB + kk * 32 + xHalf);
                uint32_t ke[2] = {kq[0], kq[2]};
                uint32_t ko[2] = {kq[1], kq[3]};
                mma_f16(s[2 * nfp], qa[kk], ke);
                mma_f16(s[2 * nfp + 1], qa[kk], ko);
            }
        }

        // ---- scale + mask ----
        const bool diagc = (c >= 2 * qt);
#pragma unroll
        for (int nf = 0; nf < 8; nf++) {
#pragma unroll
            for (int j = 0; j < 4; j++) {
                float v = s[nf][j] * 0.125f;
                if (diagc) {
                    const int col = c * ST + nf * 8 + 2 * (lane & 3) + (j & 1);
                    const int row = rowa + ((j >> 1) << 3);
                    if (col > row) v = -1e30f;
                }
                s[nf][j] = v;
            }
        }

        // ---- online softmax (warp-local, quad shuffles) ----
        float rma = -1e30f, rmb = -1e30f;
#pragma unroll
        for (int nf = 0; nf < 8; nf++) {
            rma = fmaxf(rma, fmaxf(s[nf][0], s[nf][1]));
            rmb = fmaxf(rmb, fmaxf(s[nf][2], s[nf][3]));
        }
        rma = fmaxf(rma, __shfl_xor_sync(0xffffffffu, rma, 1));
        rma = fmaxf(rma, __shfl_xor_sync(0xffffffffu, rma, 2));
        rmb = fmaxf(rmb, __shfl_xor_sync(0xffffffffu, rmb, 1));
        rmb = fmaxf(rmb, __shfl_xor_sync(0xffffffffu, rmb, 2));

        const float mna = fmaxf(m_[0], rma);
        const float mnb = fmaxf(m_[1], rmb);
        const float ca = __expf(m_[0] - mna);
        const float cb = __expf(m_[1] - mnb);
        float sa = 0.0f, sbv = 0.0f;
#pragma unroll
        for (int nf = 0; nf < 8; nf++) {
            s[nf][0] = __expf(s[nf][0] - mna);
            s[nf][1] = __expf(s[nf][1] - mna);
            s[nf][2] = __expf(s[nf][2] - mnb);
            s[nf][3] = __expf(s[nf][3] - mnb);
            sa += s[nf][0] + s[nf][1];
            sbv += s[nf][2] + s[nf][3];
        }
        sa += __shfl_xor_sync(0xffffffffu, sa, 1);
        sa += __shfl_xor_sync(0xffffffffu, sa, 2);
        sbv += __shfl_xor_sync(0xffffffffu, sbv, 1);
        sbv += __shfl_xor_sync(0xffffffffu, sbv, 2);
        l_[0] = l_[0] * ca + sa;
        l_[1] = l_[1] * cb + sbv;
        m_[0] = mna;
        m_[1] = mnb;
#pragma unroll
        for (int nf = 0; nf < 8; nf++) {
            o[nf][0] *= ca;
            o[nf][1] *= ca;
            o[nf][2] *= cb;
            o[nf][3] *= cb;
        }

        // ---- O += P V (single fp16 P) ----
#pragma unroll
        for (int kk = 0; kk < 4; kk++) {
            uint32_t ph[4];
            __half2 t0 = __floats2half2_rn(s[2 * kk][0], s[2 * kk][1]);
            __half2 t1 = __floats2half2_rn(s[2 * kk][2], s[2 * kk][3]);
            __half2 t2 = __floats2half2_rn(s[2 * kk + 1][0], s[2 * kk + 1][1]);
            __half2 t3 = __floats2half2_rn(s[2 * kk + 1][2], s[2 * kk + 1][3]);
            ph[0] = *(uint32_t*)&t0;
            ph[1] = *(uint32_t*)&t1;
            ph[2] = *(uint32_t*)&t2;
            ph[3] = *(uint32_t*)&t3;
#pragma unroll
            for (int nf = 0; nf < 8; nf++) {
                uint32_t vf[2];
                const uint32_t vo = (kk * 16 + (lane & 15)) * KROWB + nf * 16;
                ldsm2t(vf, st + KVTILE + vo);
                mma_f16(o[nf], ph, vf);
            }
        }
        // no trailing barrier: 3-stage ring makes overwrite safe with the
        // single top-of-loop barrier
    }

    // ---- epilogue: normalize, emit fp16 for the w_o GEMM ----
    const int b = bh >> 4;
    const int h = bh & 15;
    const float ia = 1.0f / l_[0];
    const float ib = 1.0f / l_[1];
#pragma unroll
    for (int nf = 0; nf < 8; nf++) {
        const int e = h * 64 + nf * 8 + 2 * (lane & 3);
        __half2 hv = __floats2half2_rn(o[nf][0] * ia, o[nf][1] * ia);
        size_t idx = (size_t)(b * SEQL + rowa) * EMB + e;
        *(uint32_t*)&O16[idx] = *(uint32_t*)&hv;
        hv = __floats2half2_rn(o[nf][2] * ib, o[nf][3] * ib);
        idx = (size_t)(b * SEQL + rowa + 8) * EMB + e;
        *(uint32_t*)&O16[idx] = *(uint32_t*)&hv;
    }
}

// ---------------- launch -----------------------------------------------------
extern "C" void kernel_launch(void* const* d_in, const int* in_sizes, int n_in,
                              void* d_out, int out_size) {
    const float* x = (const float*)d_in[0];
    const float* w_q = (const float*)d_in[1];
    const float* w_k = (const float*)d_in[2];
    const float* w_v = (const float*)d_in[3];
    const float* w_o = (const float*)d_in[4];
    float* out = (float*)d_out;

    __half *x16, *a16, *wq16, *wk16, *wv16, *wo16, *q16, *k16, *v16;
    cudaGetSymbolAddress((void**)&x16, g_x16);
    cudaGetSymbolAddress((void**)&a16, g_a16);
    cudaGetSymbolAddress((void**)&wq16, g_wq16);
    cudaGetSymbolAddress((void**)&wk16, g_wk16);
    cudaGetSymbolAddress((void**)&wv16, g_wv16);
    cudaGetSymbolAddress((void**)&wo16, g_wo16);
    cudaGetSymbolAddress((void**)&q16, g_q16);
    cudaGetSymbolAddress((void**)&k16, g_k16);
    cudaGetSymbolAddress((void**)&v16, g_v16);

    cudaFuncSetAttribute(gemm_qkv, cudaFuncAttributeMaxDynamicSharedMemorySize, SM_TOTAL);
    cudaFuncSetAttribute(gemm_out, cudaFuncAttributeMaxDynamicSharedMemorySize, SM_TOTAL);
    cudaFuncSetAttribute(attn_mma, cudaFuncAttributeMaxDynamicSharedMemorySize, AT_SMEM);

    cvt_all<<<1024 + 4 * 256, 256>>>(x, w_q, w_k, w_v, w_o,
                                     x16, wq16, wk16, wv16, wo16);

    dim3 qkvgrid(24, 32);  // x: 3 weights x 8 n-tiles; y: 32 m-tiles
    gemm_qkv<<<qkvgrid, 256, SM_TOTAL>>>(x16, wq16, wk16, wv16, q16, k16, v16);

    attn_mma<<<(SEQL / QT) * BSZ * NH, 256, AT_SMEM>>>(q16, k16, v16, a16);

    dim3 ogrid(8, 32);
    gemm_out<<<ogrid, 256, SM_TOTAL>>>(a16, wo16, out);
}